// round 7
// baseline (speedup 1.0000x reference)
#include <cuda_runtime.h>

// B=2, C=4, D=64, H=256, W=256; channels 1..3 of pred/trgt.
// scale(10)/(2*DELTA=10) cancels; vorticity linear -> stencil on (pred-trgt).
// keep voxel <=> min over 3^3 mask neighborhood == 1 (center included).

constexpr int DN = 64, HN = 256, WN = 256;
constexpr long sD = (long)HN * WN;          // 65536
constexpr long sH = WN;                     // 256
constexpr long CS = (long)DN * HN * WN;     // 4194304
constexpr int HT = 4;                       // h rows per block
constexpr int NHX = 64;                     // ceil(254/4)
constexpr int NPART = NHX * 62 * 2;         // 7936 blocks

__device__ float2 g_part[NPART];
__device__ int g_counter;                   // zero-init; self-resets each launch

__device__ __forceinline__ float4 ld4(const float* p) {
    return __ldg(reinterpret_cast<const float4*>(p));
}
__device__ __forceinline__ float4 min4(float4 a, float4 b) {
    return make_float4(fminf(a.x,b.x), fminf(a.y,b.y), fminf(a.z,b.z), fminf(a.w,b.w));
}
__device__ __forceinline__ float4 sub4(float4 a, float4 b) {
    return make_float4(a.x-b.x, a.y-b.y, a.z-b.z, a.w-b.w);
}
// (p[+off]-t[+off]) - (p[-off]-t[-off])
__device__ __forceinline__ float4 dd4(const float* p, const float* t, long off) {
    return sub4(sub4(ld4(p + off), ld4(t + off)), sub4(ld4(p - off), ld4(t - off)));
}

// Grid: (NHX, 62, 2)  block: 256 = 4 h-rows x 64 w-threads (float4 each).
__global__ __launch_bounds__(256) void vort_kernel(
    const float* __restrict__ pred,
    const float* __restrict__ trgt,
    const float* __restrict__ mask,
    float* __restrict__ out)
{
    const int tid  = threadIdx.x;
    const int row  = tid >> 6;               // 0..3
    const int t    = tid & 63;               // w-group
    const int lane = tid & 31;
    const int w4   = t << 2;                 // first w of this thread
    const int h0   = 1 + blockIdx.x * HT;
    const int h    = h0 + row;
    const int hc   = min(h, HN - 2);         // clamp; h>254 discarded later
    const int d    = 1 + blockIdx.y;         // 1..62
    const int b    = blockIdx.z;

    // ---- stencil on (pred - trgt): issue these wide loads first ----
    const long pb = (long)b * 4 * CS + (long)d * sD + (long)hc * sH + w4;
    const float* pu = pred + pb + 1 * CS;
    const float* pv = pred + pb + 2 * CS;
    const float* pw = pred + pb + 3 * CS;
    const float* tu = trgt + pb + 1 * CS;
    const float* tv = trgt + pb + 2 * CS;
    const float* tw = trgt + pb + 3 * CS;

    float4 du_d = dd4(pu, tu, sD);           // du/dD
    float4 du_h = dd4(pu, tu, sH);           // du/dH
    float4 dv_d = dd4(pv, tv, sD);           // dv/dD
    float4 dw_h = dd4(pw, tw, sH);           // dw/dH
    float4 vc   = sub4(ld4(pv), ld4(tv));    // center v diff
    float4 wc   = sub4(ld4(pw), ld4(tw));    // center w diff

    // w-neighbors of the float4 via warp shuffle of the diff; boundary lanes
    // (and block w-edges) fall back to predicated single-lane LDG (1 wf each).
    float vLn = __shfl_up_sync(0xffffffffu,   vc.w, 1);
    float wLn = __shfl_up_sync(0xffffffffu,   wc.w, 1);
    float vRn = __shfl_down_sync(0xffffffffu, vc.x, 1);
    float wRn = __shfl_down_sync(0xffffffffu, wc.x, 1);
    float vL, vR, wL, wR;
    if (lane == 0) {
        const long eL = (t > 0) ? -1 : 0;    // w4==0 edge discarded anyway
        vL = __ldg(pv + eL) - __ldg(tv + eL);
        wL = __ldg(pw + eL) - __ldg(tw + eL);
    } else { vL = vLn; wL = wLn; }
    if (lane == 31) {
        const long eR = (t < 63) ? 4 : 3;    // w==255 edge discarded anyway
        vR = __ldg(pv + eR) - __ldg(tv + eR);
        wR = __ldg(pw + eR) - __ldg(tw + eR);
    } else { vR = vRn; wR = wRn; }

    float4 dv_w = make_float4(vc.y - vL, vc.z - vc.x, vc.w - vc.y, vR - vc.z);
    float4 dw_w = make_float4(wc.y - wL, wc.z - wc.x, wc.w - wc.y, wR - wc.z);

    // vor_x = dw/dH - dv/dD ; vor_y = du/dD - dw/dW ; vor_z = dv/dW - du/dH
    float4 vx = sub4(dw_h, dv_d);
    float4 vy = sub4(du_d, dw_w);
    float4 vz = sub4(dv_w, du_h);

    // ---- cooperative mask z-min: 6 h-rows x 3 z-planes loaded once/block ----
    __shared__ float shz[HT + 2][WN];
    {
        const float* mpl = mask + (long)b * DN * sD + (long)d * sD;
        #pragma unroll
        for (int i = tid; i < (HT + 2) * 64; i += 256) {
            int r  = i >> 6;                  // 0..5
            int wg = (i & 63) << 2;
            int hm = min(h0 - 1 + r, HN - 1);
            const float* p = mpl + (long)hm * sH + wg;
            float4 z = min4(ld4(p - sD), min4(ld4(p), ld4(p + sD)));
            *reinterpret_cast<float4*>(&shz[r][wg]) = z;
        }
    }
    __syncthreads();

    // y-min over rows row..row+2, then w-min per component
    float4 z0 = *reinterpret_cast<const float4*>(&shz[row    ][w4]);
    float4 z1 = *reinterpret_cast<const float4*>(&shz[row + 1][w4]);
    float4 z2 = *reinterpret_cast<const float4*>(&shz[row + 2][w4]);
    float4 cm = min4(z0, min4(z1, z2));
    const int wl = max(w4 - 1, 0), wr = min(w4 + 4, WN - 1);
    float cmL = fminf(shz[row][wl], fminf(shz[row + 1][wl], shz[row + 2][wl]));
    float cmR = fminf(shz[row][wr], fminf(shz[row + 1][wr], shz[row + 2][wr]));

    float numer = 0.0f;
    float den   = 0.0f;
    if (h <= HN - 2) {
        float k0 = fminf(cmL,  fminf(cm.x, cm.y));
        float k1 = fminf(cm.x, fminf(cm.y, cm.z));
        float k2 = fminf(cm.y, fminf(cm.z, cm.w));
        float k3 = fminf(cm.z, fminf(cm.w, cmR));
        if (w4 > 0 && k0 > 0.5f) { numer += sqrtf(vx.x*vx.x + vy.x*vy.x + vz.x*vz.x); den += 1.0f; }
        if (k1 > 0.5f)           { numer += sqrtf(vx.y*vx.y + vy.y*vy.y + vz.y*vz.y); den += 1.0f; }
        if (k2 > 0.5f)           { numer += sqrtf(vx.z*vx.z + vy.z*vy.z + vz.z*vz.z); den += 1.0f; }
        if (w4 < WN - 4 && k3 > 0.5f) { numer += sqrtf(vx.w*vx.w + vy.w*vy.w + vz.w*vz.w); den += 1.0f; }
    }

    // ---- block reduction (8 warps) ----
    #pragma unroll
    for (int s = 16; s; s >>= 1) {
        numer += __shfl_down_sync(0xffffffffu, numer, s);
        den   += __shfl_down_sync(0xffffffffu, den,   s);
    }
    __shared__ float wn[8], wd[8];
    const int wid = tid >> 5;
    if (lane == 0) { wn[wid] = numer; wd[wid] = den; }
    __syncthreads();

    __shared__ bool isLast;
    if (wid == 0) {
        float n2 = (lane < 8) ? wn[lane] : 0.0f;
        float d2 = (lane < 8) ? wd[lane] : 0.0f;
        #pragma unroll
        for (int s = 4; s; s >>= 1) {
            n2 += __shfl_down_sync(0xffffffffu, n2, s);
            d2 += __shfl_down_sync(0xffffffffu, d2, s);
        }
        if (lane == 0) {
            const int bid = blockIdx.x + NHX * (blockIdx.y + 62 * blockIdx.z);
            g_part[bid] = make_float2(n2, d2);
            __threadfence();
            int prev = atomicAdd(&g_counter, 1);
            isLast = (prev == NPART - 1);
        }
    }
    __syncthreads();

    // ---- last block finalizes (no tail kernel) ----
    if (isLast) {
        __threadfence();
        double n = 0.0, dd = 0.0;
        for (int i = tid; i < NPART; i += 256) {
            float2 p = g_part[i];
            n  += (double)p.x;
            dd += (double)p.y;
        }
        #pragma unroll
        for (int s = 16; s; s >>= 1) {
            n  += __shfl_down_sync(0xffffffffu, n,  s);
            dd += __shfl_down_sync(0xffffffffu, dd, s);
        }
        __shared__ double sn[8], sd[8];
        if (lane == 0) { sn[wid] = n; sd[wid] = dd; }
        __syncthreads();
        if (wid == 0) {
            n  = (lane < 8) ? sn[lane] : 0.0;
            dd = (lane < 8) ? sd[lane] : 0.0;
            #pragma unroll
            for (int s = 4; s; s >>= 1) {
                n  += __shfl_down_sync(0xffffffffu, n,  s);
                dd += __shfl_down_sync(0xffffffffu, dd, s);
            }
            if (lane == 0) {
                out[0] = (float)(n / dd);
                g_counter = 0;              // reset for next graph replay
            }
        }
    }
}

extern "C" void kernel_launch(void* const* d_in, const int* in_sizes, int n_in,
                              void* d_out, int out_size) {
    const float* pred = (const float*)d_in[0];   // predicts (2,4,64,256,256)
    const float* trgt = (const float*)d_in[1];   // targets  (2,4,64,256,256)
    const float* mask = (const float*)d_in[2];   // masks    (2,1,64,256,256)
    float* out = (float*)d_out;

    dim3 grid(NHX, 62, 2);
    vort_kernel<<<grid, 256>>>(pred, trgt, mask, out);
}

// round 9
// speedup vs baseline: 1.0571x; 1.0571x over previous
#include <cuda_runtime.h>

// B=2, C=4, D=64, H=256, W=256; channels 1..3 of pred/trgt.
// scale(10)/(2*DELTA=10) cancels; vorticity linear -> stencil on (pred-trgt).
// keep voxel <=> min over 3^3 mask neighborhood == 1 (center included).
// Each thread: 4 w-voxels (float4) x 2 d-planes.

constexpr int DN = 64, HN = 256, WN = 256;
constexpr long sD = (long)HN * WN;          // 65536
constexpr long sH = WN;                     // 256
constexpr long CS = (long)DN * HN * WN;     // 4194304
constexpr int HT = 4;                       // h rows per block
constexpr int NHX = 64;                     // ceil(254/4)
constexpr int NDY = 31;                     // 62 d-planes / 2
constexpr int NPART = NHX * NDY * 2;        // 3968 blocks

__device__ float2 g_part[NPART];
__device__ int g_counter;                   // zero-init; self-resets each launch

__device__ __forceinline__ float4 ld4(const float* p) {
    return __ldg(reinterpret_cast<const float4*>(p));
}
__device__ __forceinline__ float4 min4(float4 a, float4 b) {
    return make_float4(fminf(a.x,b.x), fminf(a.y,b.y), fminf(a.z,b.z), fminf(a.w,b.w));
}
__device__ __forceinline__ float4 sub4(float4 a, float4 b) {
    return make_float4(a.x-b.x, a.y-b.y, a.z-b.z, a.w-b.w);
}
// (p[+off]-t[+off]) - (p[-off]-t[-off])
__device__ __forceinline__ float4 dd4(const float* p, const float* t, long off) {
    return sub4(sub4(ld4(p + off), ld4(t + off)), sub4(ld4(p - off), ld4(t - off)));
}
// min over dy of mask plane row
__device__ __forceinline__ float4 ymin3(const float* p) {
    return min4(ld4(p - sH), min4(ld4(p), ld4(p + sH)));
}

// Grid: (NHX, NDY, 2)  block: 256 = 4 h-rows x 64 w-threads.
__global__ __launch_bounds__(256) void vort_kernel(
    const float* __restrict__ pred,
    const float* __restrict__ trgt,
    const float* __restrict__ mask,
    float* __restrict__ out)
{
    const int tid  = threadIdx.x;
    const int row  = tid >> 6;               // 0..3
    const int t    = tid & 63;               // w-group
    const int lane = tid & 31;
    const int w4   = t << 2;
    const int h    = 1 + blockIdx.x * HT + row;
    const int hc   = min(h, HN - 2);         // clamp; h>254 discarded later
    const int d0   = 1 + blockIdx.y * 2;     // planes d0, d0+1  (1..62)
    const int b    = blockIdx.z;

    // ---- mask: z-column y-mins for 4 planes d0-1..d0+2 (12 f4 loads / 8 voxels) ----
    const float* mb = mask + (long)b * DN * sD + (long)d0 * sD + (long)hc * sH + w4;
    float4 zp0 = ymin3(mb - sD);
    float4 zp1 = ymin3(mb);
    float4 zp2 = ymin3(mb + sD);
    float4 zp3 = ymin3(mb + 2 * sD);
    float4 cm0 = min4(zp0, min4(zp1, zp2));
    float4 cm1 = min4(zp1, min4(zp2, zp3));

    __shared__ float cs[2][HT][WN];
    *reinterpret_cast<float4*>(&cs[0][row][w4]) = cm0;
    *reinterpret_cast<float4*>(&cs[1][row][w4]) = cm1;

    // ---- stencil on (pred - trgt), both planes (36 f4 loads, independent) ----
    const long pb = (long)b * 4 * CS + (long)d0 * sD + (long)hc * sH + w4;
    const float* pu = pred + pb + 1 * CS;
    const float* pv = pred + pb + 2 * CS;
    const float* pw = pred + pb + 3 * CS;
    const float* tu = trgt + pb + 1 * CS;
    const float* tv = trgt + pb + 2 * CS;
    const float* tw = trgt + pb + 3 * CS;

    float4 vx[2], vy[2], vz[2];
    #pragma unroll
    for (int p = 0; p < 2; p++) {
        const long o = (long)p * sD;
        float4 du_d = dd4(pu + o, tu + o, sD);
        float4 du_h = dd4(pu + o, tu + o, sH);
        float4 dv_d = dd4(pv + o, tv + o, sD);
        float4 dw_h = dd4(pw + o, tw + o, sH);
        float4 vcc  = sub4(ld4(pv + o), ld4(tv + o));
        float4 wcc  = sub4(ld4(pw + o), ld4(tw + o));

        // w-neighbors via shuffle; lanes 0/31 fall back to predicated scalar LDG
        float vLn = __shfl_up_sync(0xffffffffu,   vcc.w, 1);
        float wLn = __shfl_up_sync(0xffffffffu,   wcc.w, 1);
        float vRn = __shfl_down_sync(0xffffffffu, vcc.x, 1);
        float wRn = __shfl_down_sync(0xffffffffu, wcc.x, 1);
        float vL, vR, wL, wR;
        if (lane == 0) {
            const long eL = o + ((t > 0) ? -1 : 0);   // w4==0 edge discarded
            vL = __ldg(pv + eL) - __ldg(tv + eL);
            wL = __ldg(pw + eL) - __ldg(tw + eL);
        } else { vL = vLn; wL = wLn; }
        if (lane == 31) {
            const long eR = o + ((t < 63) ? 4 : 3);   // w==255 edge discarded
            vR = __ldg(pv + eR) - __ldg(tv + eR);
            wR = __ldg(pw + eR) - __ldg(tw + eR);
        } else { vR = vRn; wR = wRn; }

        float4 dv_w = make_float4(vcc.y - vL, vcc.z - vcc.x, vcc.w - vcc.y, vR - vcc.z);
        float4 dw_w = make_float4(wcc.y - wL, wcc.z - wcc.x, wcc.w - wcc.y, wR - wcc.z);

        vx[p] = sub4(dw_h, dv_d);   // vor_x = dw/dH - dv/dD
        vy[p] = sub4(du_d, dw_w);   // vor_y = du/dD - dw/dW
        vz[p] = sub4(dv_w, du_h);   // vor_z = dv/dW - du/dH
    }

    __syncthreads();

    float numer = 0.0f;
    float den   = 0.0f;
    if (h <= HN - 2) {
        const int wl = max(w4 - 1, 0), wr = min(w4 + 4, WN - 1);
        #pragma unroll
        for (int p = 0; p < 2; p++) {
            float4 cm = (p == 0) ? cm0 : cm1;
            float cmL = cs[p][row][wl];
            float cmR = cs[p][row][wr];
            float k0 = fminf(cmL,  fminf(cm.x, cm.y));
            float k1 = fminf(cm.x, fminf(cm.y, cm.z));
            float k2 = fminf(cm.y, fminf(cm.z, cm.w));
            float k3 = fminf(cm.z, fminf(cm.w, cmR));
            if (w4 > 0 && k0 > 0.5f) {
                numer += sqrtf(vx[p].x*vx[p].x + vy[p].x*vy[p].x + vz[p].x*vz[p].x); den += 1.0f;
            }
            if (k1 > 0.5f) {
                numer += sqrtf(vx[p].y*vx[p].y + vy[p].y*vy[p].y + vz[p].y*vz[p].y); den += 1.0f;
            }
            if (k2 > 0.5f) {
                numer += sqrtf(vx[p].z*vx[p].z + vy[p].z*vy[p].z + vz[p].z*vz[p].z); den += 1.0f;
            }
            if (w4 < WN - 4 && k3 > 0.5f) {
                numer += sqrtf(vx[p].w*vx[p].w + vy[p].w*vy[p].w + vz[p].w*vz[p].w); den += 1.0f;
            }
        }
    }

    // ---- block reduction (8 warps) ----
    #pragma unroll
    for (int s = 16; s; s >>= 1) {
        numer += __shfl_down_sync(0xffffffffu, numer, s);
        den   += __shfl_down_sync(0xffffffffu, den,   s);
    }
    __shared__ float wn[8], wd[8];
    const int wid = tid >> 5;
    if (lane == 0) { wn[wid] = numer; wd[wid] = den; }
    __syncthreads();

    __shared__ bool isLast;
    if (wid == 0) {
        float n2 = (lane < 8) ? wn[lane] : 0.0f;
        float d2 = (lane < 8) ? wd[lane] : 0.0f;
        #pragma unroll
        for (int s = 4; s; s >>= 1) {
            n2 += __shfl_down_sync(0xffffffffu, n2, s);
            d2 += __shfl_down_sync(0xffffffffu, d2, s);
        }
        if (lane == 0) {
            const int bid = blockIdx.x + NHX * (blockIdx.y + NDY * blockIdx.z);
            g_part[bid] = make_float2(n2, d2);
            __threadfence();
            int prev = atomicAdd(&g_counter, 1);
            isLast = (prev == NPART - 1);
        }
    }
    __syncthreads();

    // ---- last block finalizes (no tail kernel) ----
    if (isLast) {
        __threadfence();
        double n = 0.0, dd = 0.0;
        for (int i = tid; i < NPART; i += 256) {
            float2 p = g_part[i];
            n  += (double)p.x;
            dd += (double)p.y;
        }
        #pragma unroll
        for (int s = 16; s; s >>= 1) {
            n  += __shfl_down_sync(0xffffffffu, n,  s);
            dd += __shfl_down_sync(0xffffffffu, dd, s);
        }
        __shared__ double sn[8], sd[8];
        if (lane == 0) { sn[wid] = n; sd[wid] = dd; }
        __syncthreads();
        if (wid == 0) {
            n  = (lane < 8) ? sn[lane] : 0.0;
            dd = (lane < 8) ? sd[lane] : 0.0;
            #pragma unroll
            for (int s = 4; s; s >>= 1) {
                n  += __shfl_down_sync(0xffffffffu, n,  s);
                dd += __shfl_down_sync(0xffffffffu, dd, s);
            }
            if (lane == 0) {
                out[0] = (float)(n / dd);
                g_counter = 0;              // reset for next graph replay
            }
        }
    }
}

extern "C" void kernel_launch(void* const* d_in, const int* in_sizes, int n_in,
                              void* d_out, int out_size) {
    const float* pred = (const float*)d_in[0];   // predicts (2,4,64,256,256)
    const float* trgt = (const float*)d_in[1];   // targets  (2,4,64,256,256)
    const float* mask = (const float*)d_in[2];   // masks    (2,1,64,256,256)
    float* out = (float*)d_out;

    dim3 grid(NHX, NDY, 2);
    vort_kernel<<<grid, 256>>>(pred, trgt, mask, out);
}